// round 6
// baseline (speedup 1.0000x reference)
#include <cuda_runtime.h>
#include <math.h>
#include <stdint.h>

#define B_   8
#define L_   1024
#define D_   512
#define H_   8
#define DK_  64
#define DFF_ 2048
#define M_   (B_*L_)

// ---------------- device scratch (static: no runtime allocation) ----------------
__device__ float g_q  [B_*H_*L_*DK_];            // (B,H,L,DK)
__device__ float g_k  [B_*H_*L_*DK_];
__device__ float g_v  [B_*H_*L_*DK_];
__device__ float g_ctx[M_*D_];
__device__ float g_bufA[M_*D_];
__device__ float g_bufB[M_*D_];
__device__ float g_ff [M_*DFF_];

// ---------------- epilogue modes ----------------
enum {
    EP_QKV = 0,      // +bias, permuted write to (B,H,L,DK)
    EP_BIAS_RES = 1, // +bias +res
    EP_GELU = 2      // gelu(acc+bias), exact erf
};

// ---------------- PTX helpers ----------------
__device__ __forceinline__ uint32_t f2tf(float f) {
    uint32_t u;
    asm("cvt.rna.tf32.f32 %0, %1;" : "=r"(u) : "f"(f));
    return u;
}
__device__ __forceinline__ void mma8(float* d, const uint32_t* a, const uint32_t* b) {
    asm volatile(
        "mma.sync.aligned.m16n8k8.row.col.f32.tf32.tf32.f32 "
        "{%0,%1,%2,%3}, {%4,%5,%6,%7}, {%8,%9}, {%0,%1,%2,%3};"
        : "+f"(d[0]), "+f"(d[1]), "+f"(d[2]), "+f"(d[3])
        : "r"(a[0]), "r"(a[1]), "r"(a[2]), "r"(a[3]), "r"(b[0]), "r"(b[1]));
}
__device__ __forceinline__ void cpa16(uint32_t dst, const float* src) {
    asm volatile("cp.async.ca.shared.global [%0], [%1], 16;" :: "r"(dst), "l"(src));
}
#define CP_COMMIT() asm volatile("cp.async.commit_group;")
#define CP_WAIT(n)  asm volatile("cp.async.wait_group %0;" :: "n"(n))

// ---------------------------------------------------------------------------
// tf32 tensor-core GEMM: C = A * B^T (projections / FF only). Unchanged.
// ---------------------------------------------------------------------------
template<int EP, int BN>
__global__ void __launch_bounds__(256)
gemm_tc(const float* __restrict__ A, const float* __restrict__ Bm,
        const float* __restrict__ bias, const float* __restrict__ res,
        float* __restrict__ C,
        int N, int K, int lda, int ldb)
{
    constexpr int NI = BN / 16;
    __shared__ float As[2][128][20];
    __shared__ float Bs[2][BN][20];

    const int by = blockIdx.y, bx = blockIdx.x;
    const int tid  = threadIdx.x;
    const int lane = tid & 31;
    const int warp = tid >> 5;
    const int wm = warp & 3;
    const int wn = warp >> 2;

    const uint32_t sA = (uint32_t)__cvta_generic_to_shared(&As[0][0][0]);
    const uint32_t sB = (uint32_t)__cvta_generic_to_shared(&Bs[0][0][0]);

    float acc[2][NI][4];
#pragma unroll
    for (int mi = 0; mi < 2; mi++)
#pragma unroll
        for (int ni = 0; ni < NI; ni++)
#pragma unroll
            for (int r = 0; r < 4; r++) acc[mi][ni][r] = 0.f;

    const int arow0 = tid >> 2;
    const int akq   = (tid & 3) << 2;
    const int nT = K >> 4;

    {
#pragma unroll
        for (int e = 0; e < 2; e++) {
            int row = arow0 + e * 64;
            cpa16(sA + (uint32_t)((row * 20 + akq) * 4),
                  A + (long)(by * 128 + row) * lda + akq);
        }
#pragma unroll
        for (int e = 0; e < BN / 64; e++) {
            int row = arow0 + e * 64;
            cpa16(sB + (uint32_t)((row * 20 + akq) * 4),
                  Bm + (long)(bx * BN + row) * ldb + akq);
        }
        CP_COMMIT();
    }

    for (int kt = 0; kt < nT; kt++) {
        const int st = kt & 1;
        if (kt + 1 < nT) {
            const int ns = st ^ 1;
            const int k0 = (kt + 1) << 4;
#pragma unroll
            for (int e = 0; e < 2; e++) {
                int row = arow0 + e * 64;
                cpa16(sA + (uint32_t)(((ns * 128 + row) * 20 + akq) * 4),
                      A + (long)(by * 128 + row) * lda + k0 + akq);
            }
#pragma unroll
            for (int e = 0; e < BN / 64; e++) {
                int row = arow0 + e * 64;
                cpa16(sB + (uint32_t)(((ns * BN + row) * 20 + akq) * 4),
                      Bm + (long)(bx * BN + row) * ldb + k0 + akq);
            }
            CP_COMMIT();
            CP_WAIT(1);
        } else {
            CP_WAIT(0);
        }
        __syncthreads();

#pragma unroll
        for (int ks = 0; ks < 2; ks++) {
            const int kc = (ks << 3) + (lane & 3);
            uint32_t afr[2][4], bfr[NI][2];
#pragma unroll
            for (int mi = 0; mi < 2; mi++) {
                const int r = wm * 32 + mi * 16 + (lane >> 2);
                afr[mi][0] = f2tf(As[st][r][kc]);
                afr[mi][1] = f2tf(As[st][r + 8][kc]);
                afr[mi][2] = f2tf(As[st][r][kc + 4]);
                afr[mi][3] = f2tf(As[st][r + 8][kc + 4]);
            }
#pragma unroll
            for (int ni = 0; ni < NI; ni++) {
                const int r = wn * (BN / 2) + ni * 8 + (lane >> 2);
                bfr[ni][0] = f2tf(Bs[st][r][kc]);
                bfr[ni][1] = f2tf(Bs[st][r][kc + 4]);
            }
#pragma unroll
            for (int mi = 0; mi < 2; mi++)
#pragma unroll
                for (int ni = 0; ni < NI; ni++)
                    mma8(acc[mi][ni], afr[mi], bfr[ni]);
        }
        __syncthreads();
    }

#pragma unroll
    for (int mi = 0; mi < 2; mi++) {
#pragma unroll
        for (int ni = 0; ni < NI; ni++) {
            const int m = by * 128 + wm * 32 + mi * 16 + (lane >> 2);
            const int n = bx * BN + wn * (BN / 2) + ni * 8 + ((lane & 3) << 1);
            float d0 = acc[mi][ni][0], d1 = acc[mi][ni][1];
            float d2 = acc[mi][ni][2], d3 = acc[mi][ni][3];

            if (EP == EP_QKV) {
                float2 bb = *(const float2*)(bias + n);
                const int h = n >> 6, dk = n & 63;
                {
                    int b = m >> 10, l = m & 1023;
                    *(float2*)(C + ((long)(b * H_ + h) * L_ + l) * DK_ + dk) =
                        make_float2(d0 + bb.x, d1 + bb.y);
                }
                {
                    int mm = m + 8;
                    int b = mm >> 10, l = mm & 1023;
                    *(float2*)(C + ((long)(b * H_ + h) * L_ + l) * DK_ + dk) =
                        make_float2(d2 + bb.x, d3 + bb.y);
                }
            } else if (EP == EP_BIAS_RES) {
                float2 bb = *(const float2*)(bias + n);
                float2 r0 = *(const float2*)(res + (long)m * N + n);
                float2 r1 = *(const float2*)(res + (long)(m + 8) * N + n);
                *(float2*)(C + (long)m * N + n) =
                    make_float2(d0 + bb.x + r0.x, d1 + bb.y + r0.y);
                *(float2*)(C + (long)(m + 8) * N + n) =
                    make_float2(d2 + bb.x + r1.x, d3 + bb.y + r1.y);
            } else if (EP == EP_GELU) {
                float2 bb = *(const float2*)(bias + n);
                float t0 = d0 + bb.x, t1 = d1 + bb.y;
                float t2 = d2 + bb.x, t3 = d3 + bb.y;
                t0 = 0.5f * t0 * (1.f + erff(t0 * 0.70710678118654752f));
                t1 = 0.5f * t1 * (1.f + erff(t1 * 0.70710678118654752f));
                t2 = 0.5f * t2 * (1.f + erff(t2 * 0.70710678118654752f));
                t3 = 0.5f * t3 * (1.f + erff(t3 * 0.70710678118654752f));
                *(float2*)(C + (long)m * N + n)       = make_float2(t0, t1);
                *(float2*)(C + (long)(m + 8) * N + n) = make_float2(t2, t3);
            }
        }
    }
}

// ---------------------------------------------------------------------------
// Fused flash attention: softmax(Q K^T / 8 - 0.1|m-n|) V  -> ctx (B,L,D)
// R5 changes vs R3/R4:
//  * K/V/Q converted to tf32 bit-patterns ONCE in smem (each thread converts
//    the elements it cp.async'd: own-data, no extra barrier). Fragment loads
//    are raw bit aliases — removes ~256 cvt per chunk per thread.
//  * P converted at store time (bits in smem), loads are aliases.
//  * V smem stride 72 (was 68): V fragment reads now bank-conflict-free.
// Layout (floats): Q 128x68 | K 2x64x68 | V 2x64x72 | P 8x16x68  (~141 KB)
// ---------------------------------------------------------------------------
#define QS_OFF 0
#define KS_OFF 8704
#define VS_OFF 17408
#define PS_OFF 26624
#define SMEM_FLASH_FLOATS 35328
#define SMEM_FLASH_BYTES  (SMEM_FLASH_FLOATS * 4)
#define KV_STG 4352        // K stage stride (64*68)
#define VS_STG 4608        // V stage stride (64*72)

__global__ void __launch_bounds__(256)
flash_k(const float* __restrict__ q, const float* __restrict__ k,
        const float* __restrict__ v, float* __restrict__ ctx)
{
    extern __shared__ float sm[];
    const uint32_t smB = (uint32_t)__cvta_generic_to_shared(sm);

    const int tid  = threadIdx.x;
    const int lane = tid & 31;
    const int w    = tid >> 5;
    const int r    = lane >> 2;     // 0..7
    const int qv   = lane & 3;      // 0..3
    const int q0   = blockIdx.x * 128;
    const int z    = blockIdx.y;    // b*H + h

    const float* kz = k + (long)z * L_ * DK_;
    const float* vz = v + (long)z * L_ * DK_;

    // ---- prologue: Q tile (group 0), chunk 0 of K/V (group 1) ----
    {
        const float* Qg = q + ((long)z * L_ + q0) * DK_;
#pragma unroll
        for (int e = 0; e < 8; e++) {
            int idx = tid + e * 256;
            int row = idx >> 4, c4 = (idx & 15) << 2;
            cpa16(smB + (uint32_t)((QS_OFF + row * 68 + c4) << 2),
                  Qg + (long)row * DK_ + c4);
        }
        CP_COMMIT();
#pragma unroll
        for (int e = 0; e < 4; e++) {
            int idx = tid + e * 256;
            int row = idx >> 4, c4 = (idx & 15) << 2;
            cpa16(smB + (uint32_t)((KS_OFF + row * 68 + c4) << 2),
                  kz + (long)row * DK_ + c4);
            cpa16(smB + (uint32_t)((VS_OFF + row * 72 + c4) << 2),
                  vz + (long)row * DK_ + c4);
        }
        CP_COMMIT();
        CP_WAIT(1);     // Q group done (this thread's copies visible to it)
        // convert own Q elements to tf32 bits, in place
#pragma unroll
        for (int e = 0; e < 8; e++) {
            int idx = tid + e * 256;
            int row = idx >> 4, c4 = (idx & 15) << 2;
            float4* p = (float4*)&sm[QS_OFF + row * 68 + c4];
            float4 vq = *p;
            vq.x = __uint_as_float(f2tf(vq.x));
            vq.y = __uint_as_float(f2tf(vq.y));
            vq.z = __uint_as_float(f2tf(vq.z));
            vq.w = __uint_as_float(f2tf(vq.w));
            *p = vq;
        }
    }

    float o[8][4];
#pragma unroll
    for (int j = 0; j < 8; j++)
#pragma unroll
        for (int t = 0; t < 4; t++) o[j][t] = 0.f;
    float m0 = -1e30f, m1 = -1e30f, l0 = 0.f, l1 = 0.f;

    const int qrow = w * 16 + r;               // local q row (first of pair)
    const float mg0 = (float)(q0 + qrow);
    float* Pw = sm + PS_OFF + w * 16 * 68;

    for (int c = 0; c < 16; c++) {
        const int st = c & 1;
        if (c + 1 < 16) {
            const int ns = st ^ 1;
            const float* Kg = kz + (long)(c + 1) * 64 * DK_;
            const float* Vg = vz + (long)(c + 1) * 64 * DK_;
#pragma unroll
            for (int e = 0; e < 4; e++) {
                int idx = tid + e * 256;
                int row = idx >> 4, c4 = (idx & 15) << 2;
                cpa16(smB + (uint32_t)((KS_OFF + ns * KV_STG + row * 68 + c4) << 2),
                      Kg + (long)row * DK_ + c4);
                cpa16(smB + (uint32_t)((VS_OFF + ns * VS_STG + row * 72 + c4) << 2),
                      Vg + (long)row * DK_ + c4);
            }
            CP_COMMIT();
            CP_WAIT(1);
        } else {
            CP_WAIT(0);
        }

        // ---- convert own K/V elements of stage st to tf32 bits (pre-barrier:
        //      this thread issued these copies; stage last read 2 chunks ago) ----
#pragma unroll
        for (int e = 0; e < 4; e++) {
            int idx = tid + e * 256;
            int row = idx >> 4, c4 = (idx & 15) << 2;
            float4* pk = (float4*)&sm[KS_OFF + st * KV_STG + row * 68 + c4];
            float4 vk = *pk;
            vk.x = __uint_as_float(f2tf(vk.x));
            vk.y = __uint_as_float(f2tf(vk.y));
            vk.z = __uint_as_float(f2tf(vk.z));
            vk.w = __uint_as_float(f2tf(vk.w));
            *pk = vk;
            float4* pv = (float4*)&sm[VS_OFF + st * VS_STG + row * 72 + c4];
            float4 vv = *pv;
            vv.x = __uint_as_float(f2tf(vv.x));
            vv.y = __uint_as_float(f2tf(vv.y));
            vv.z = __uint_as_float(f2tf(vv.z));
            vv.w = __uint_as_float(f2tf(vv.w));
            *pv = vv;
        }
        __syncthreads();

        // ---- S = Q K^T over this 64-key chunk (raw bit fragment loads) ----
        float s[8][4];
#pragma unroll
        for (int j = 0; j < 8; j++)
#pragma unroll
            for (int t = 0; t < 4; t++) s[j][t] = 0.f;

        const float* Ks = sm + KS_OFF + st * KV_STG;
        const float* Vs = sm + VS_OFF + st * VS_STG;
#pragma unroll
        for (int ks = 0; ks < 8; ks++) {
            const int kc = ks * 8 + qv;
            uint32_t qa[4];
            qa[0] = __float_as_uint(sm[QS_OFF + qrow * 68 + kc]);
            qa[1] = __float_as_uint(sm[QS_OFF + (qrow + 8) * 68 + kc]);
            qa[2] = __float_as_uint(sm[QS_OFF + qrow * 68 + kc + 4]);
            qa[3] = __float_as_uint(sm[QS_OFF + (qrow + 8) * 68 + kc + 4]);
#pragma unroll
            for (int j = 0; j < 8; j++) {
                const int krow = j * 8 + r;
                uint32_t kb[2];
                kb[0] = __float_as_uint(Ks[krow * 68 + kc]);
                kb[1] = __float_as_uint(Ks[krow * 68 + kc + 4]);
                mma8(s[j], qa, kb);
            }
        }

        // ---- scale + ALiBi bias ----
#pragma unroll
        for (int j = 0; j < 8; j++) {
            const float nb = (float)(c * 64 + j * 8 + 2 * qv);
            s[j][0] = s[j][0] * 0.125f - 0.1f * fabsf(mg0 - nb);
            s[j][1] = s[j][1] * 0.125f - 0.1f * fabsf(mg0 - nb - 1.f);
            s[j][2] = s[j][2] * 0.125f - 0.1f * fabsf(mg0 + 8.f - nb);
            s[j][3] = s[j][3] * 0.125f - 0.1f * fabsf(mg0 + 8.f - nb - 1.f);
        }

        // ---- online softmax update ----
        float mx0 = -1e30f, mx1 = -1e30f;
#pragma unroll
        for (int j = 0; j < 8; j++) {
            mx0 = fmaxf(mx0, fmaxf(s[j][0], s[j][1]));
            mx1 = fmaxf(mx1, fmaxf(s[j][2], s[j][3]));
        }
        mx0 = fmaxf(mx0, __shfl_xor_sync(0xffffffffu, mx0, 1));
        mx0 = fmaxf(mx0, __shfl_xor_sync(0xffffffffu, mx0, 2));
        mx1 = fmaxf(mx1, __shfl_xor_sync(0xffffffffu, mx1, 1));
        mx1 = fmaxf(mx1, __shfl_xor_sync(0xffffffffu, mx1, 2));

        const float nm0 = fmaxf(m0, mx0);
        const float nm1 = fmaxf(m1, mx1);
        const float sc0 = __expf(m0 - nm0);
        const float sc1 = __expf(m1 - nm1);
        m0 = nm0; m1 = nm1;

        float rs0 = 0.f, rs1 = 0.f;
#pragma unroll
        for (int j = 0; j < 8; j++) {
            s[j][0] = __expf(s[j][0] - m0);
            s[j][1] = __expf(s[j][1] - m0);
            s[j][2] = __expf(s[j][2] - m1);
            s[j][3] = __expf(s[j][3] - m1);
            rs0 += s[j][0] + s[j][1];
            rs1 += s[j][2] + s[j][3];
        }
        rs0 += __shfl_xor_sync(0xffffffffu, rs0, 1);
        rs0 += __shfl_xor_sync(0xffffffffu, rs0, 2);
        rs1 += __shfl_xor_sync(0xffffffffu, rs1, 1);
        rs1 += __shfl_xor_sync(0xffffffffu, rs1, 2);
        l0 = l0 * sc0 + rs0;
        l1 = l1 * sc1 + rs1;

#pragma unroll
        for (int j = 0; j < 8; j++) {
            o[j][0] *= sc0; o[j][1] *= sc0;
            o[j][2] *= sc1; o[j][3] *= sc1;
        }

        // ---- stage P as tf32 bits (cvt at store), then O += P V ----
#pragma unroll
        for (int j = 0; j < 8; j++) {
            *(float2*)&Pw[r * 68 + j * 8 + 2 * qv] =
                make_float2(__uint_as_float(f2tf(s[j][0])),
                            __uint_as_float(f2tf(s[j][1])));
            *(float2*)&Pw[(r + 8) * 68 + j * 8 + 2 * qv] =
                make_float2(__uint_as_float(f2tf(s[j][2])),
                            __uint_as_float(f2tf(s[j][3])));
        }
        __syncwarp();

#pragma unroll
        for (int ks = 0; ks < 8; ks++) {
            const int kc = ks * 8 + qv;
            uint32_t pa[4];
            pa[0] = __float_as_uint(Pw[r * 68 + kc]);
            pa[1] = __float_as_uint(Pw[(r + 8) * 68 + kc]);
            pa[2] = __float_as_uint(Pw[r * 68 + kc + 4]);
            pa[3] = __float_as_uint(Pw[(r + 8) * 68 + kc + 4]);
#pragma unroll
            for (int j = 0; j < 8; j++) {
                uint32_t vb[2];
                vb[0] = __float_as_uint(Vs[kc * 72 + j * 8 + r]);
                vb[1] = __float_as_uint(Vs[(kc + 4) * 72 + j * 8 + r]);
                mma8(o[j], pa, vb);
            }
        }
        __syncthreads();
    }

    // ---- epilogue: O / l -> ctx (B,L,D) ----
    const float inv0 = 1.0f / l0;
    const float inv1 = 1.0f / l1;
    const int b = z >> 3, h = z & 7;
    const int mglob = q0 + qrow;
    float* C0 = ctx + ((long)b * L_ + mglob) * D_ + h * DK_;
    float* C1 = C0 + 8 * D_;
#pragma unroll
    for (int j = 0; j < 8; j++) {
        const int n = j * 8 + 2 * qv;
        *(float2*)(C0 + n) = make_float2(o[j][0] * inv0, o[j][1] * inv0);
        *(float2*)(C1 + n) = make_float2(o[j][2] * inv1, o[j][3] * inv1);
    }
}

// ---------------------------------------------------------------------------
// Fused moving_avg (window 25, zero-pad 12) + LayerNorm. 16 rows / block.
// ---------------------------------------------------------------------------
__global__ void __launch_bounds__(256)
mvln_k(const float* __restrict__ X, float* __restrict__ Y,
       const float* __restrict__ g, const float* __restrict__ b)
{
    __shared__ float tr[16][D_];
    const int bidx = blockIdx.x;
    const int bb = bidx >> 6;
    const int l0 = (bidx & 63) * 16;
    const float* Xb = X + (long)bb * L_ * D_;
    const int tid = threadIdx.x;

    for (int task = tid; task < 16 * 128; task += 256) {
        const int r  = task >> 7;
        const int dg = task & 127;
        const int l  = l0 + r;
        float4 s = make_float4(0.f, 0.f, 0.f, 0.f);
        const int j0 = l - 12;
#pragma unroll
        for (int j = 0; j < 25; j++) {
            const int ll = j0 + j;
            if (ll >= 0 && ll < L_) {
                float4 xv = *(const float4*)(Xb + (long)ll * D_ + (dg << 2));
                s.x += xv.x; s.y += xv.y; s.z += xv.z; s.w += xv.w;
            }
        }
        const float inv = 1.f / 25.f;
        *(float4*)&tr[r][dg << 2] = make_float4(s.x * inv, s.y * inv, s.z * inv, s.w * inv);
    }
    __syncthreads();

    const int wid = tid >> 5, lane = tid & 31;
#pragma unroll
    for (int rr = 0; rr < 2; rr++) {
        const int r = wid * 2 + rr;
        float sum = 0.f, sq = 0.f;
        for (int d = lane; d < D_; d += 32) {
            float v = tr[r][d];
            sum += v; sq += v * v;
        }
#pragma unroll
        for (int o = 16; o; o >>= 1) {
            sum += __shfl_xor_sync(0xffffffffu, sum, o);
            sq  += __shfl_xor_sync(0xffffffffu, sq, o);
        }
        const float mu   = sum * (1.f / D_);
        const float var  = sq * (1.f / D_) - mu * mu;
        const float rstd = rsqrtf(var + 1e-5f);
        float* Yo = Y + ((long)bb * L_ + l0 + r) * D_;
        for (int d = lane; d < D_; d += 32)
            Yo[d] = (tr[r][d] - mu) * rstd * g[d] + b[d];
    }
}

// ---------------------------------------------------------------------------
extern "C" void kernel_launch(void* const* d_in, const int* in_sizes, int n_in,
                              void* d_out, int out_size)
{
    (void)in_sizes; (void)n_in; (void)out_size;
    const float* x     = (const float*)d_in[0];
    const float* enc   = (const float*)d_in[1];
    const float* sa_Wq = (const float*)d_in[2];  const float* sa_bq = (const float*)d_in[3];
    const float* sa_Wk = (const float*)d_in[4];  const float* sa_bk = (const float*)d_in[5];
    const float* sa_Wv = (const float*)d_in[6];  const float* sa_bv = (const float*)d_in[7];
    const float* sa_Wo = (const float*)d_in[8];  const float* sa_bo = (const float*)d_in[9];
    const float* ca_Wq = (const float*)d_in[10]; const float* ca_bq = (const float*)d_in[11];
    const float* ca_Wk = (const float*)d_in[12]; const float* ca_bk = (const float*)d_in[13];
    const float* ca_Wv = (const float*)d_in[14]; const float* ca_bv = (const float*)d_in[15];
    const float* ca_Wo = (const float*)d_in[16]; const float* ca_bo = (const float*)d_in[17];
    const float* ff_W1 = (const float*)d_in[18]; const float* ff_b1 = (const float*)d_in[19];
    const float* ff_W2 = (const float*)d_in[20]; const float* ff_b2 = (const float*)d_in[21];
    const float* n1_g  = (const float*)d_in[22]; const float* n1_b  = (const float*)d_in[23];
    const float* n2_g  = (const float*)d_in[24]; const float* n2_b  = (const float*)d_in[25];
    const float* n3_g  = (const float*)d_in[26]; const float* n3_b  = (const float*)d_in[27];
    float* out = (float*)d_out;

    float *q, *k, *v, *ctx, *bufA, *bufB, *ff;
    cudaGetSymbolAddress((void**)&q,    g_q);
    cudaGetSymbolAddress((void**)&k,    g_k);
    cudaGetSymbolAddress((void**)&v,    g_v);
    cudaGetSymbolAddress((void**)&ctx,  g_ctx);
    cudaGetSymbolAddress((void**)&bufA, g_bufA);
    cudaGetSymbolAddress((void**)&bufB, g_bufB);
    cudaGetSymbolAddress((void**)&ff,   g_ff);

    cudaFuncSetAttribute(flash_k, cudaFuncAttributeMaxDynamicSharedMemorySize,
                         SMEM_FLASH_BYTES);

    const dim3 thr(256);
    const dim3 gProj(D_ / 128, M_ / 128, 1);     // (4, 64)
    const dim3 gFF1(DFF_ / 128, M_ / 128, 1);    // (16, 64)
    const dim3 gFl(L_ / 128, B_ * H_, 1);        // (8, 64)
    const dim3 gMv(B_ * L_ / 16, 1, 1);

    // ===================== self-attention =====================
    gemm_tc<EP_QKV, 128><<<gProj, thr>>>(x, sa_Wq, sa_bq, nullptr, q, D_, D_, D_, D_);
    gemm_tc<EP_QKV, 128><<<gProj, thr>>>(x, sa_Wk, sa_bk, nullptr, k, D_, D_, D_, D_);
    gemm_tc<EP_QKV, 128><<<gProj, thr>>>(x, sa_Wv, sa_bv, nullptr, v, D_, D_, D_, D_);
    flash_k<<<gFl, thr, SMEM_FLASH_BYTES>>>(q, k, v, ctx);
    gemm_tc<EP_BIAS_RES, 128><<<gProj, thr>>>(ctx, sa_Wo, sa_bo, x, bufA, D_, D_, D_, D_);
    mvln_k<<<gMv, thr>>>(bufA, bufB, n1_g, n1_b);

    // ===================== cross-attention =====================
    gemm_tc<EP_QKV, 128><<<gProj, thr>>>(bufB, ca_Wq, ca_bq, nullptr, q, D_, D_, D_, D_);
    gemm_tc<EP_QKV, 128><<<gProj, thr>>>(enc,  ca_Wk, ca_bk, nullptr, k, D_, D_, D_, D_);
    gemm_tc<EP_QKV, 128><<<gProj, thr>>>(enc,  ca_Wv, ca_bv, nullptr, v, D_, D_, D_, D_);
    flash_k<<<gFl, thr, SMEM_FLASH_BYTES>>>(q, k, v, ctx);
    gemm_tc<EP_BIAS_RES, 128><<<gProj, thr>>>(ctx, ca_Wo, ca_bo, bufB, bufA, D_, D_, D_, D_);
    mvln_k<<<gMv, thr>>>(bufA, bufB, n2_g, n2_b);

    // ===================== feed-forward =====================
    gemm_tc<EP_GELU, 128><<<gFF1, thr>>>(bufB, ff_W1, ff_b1, nullptr, ff, DFF_, D_, D_, D_);
    gemm_tc<EP_BIAS_RES, 128><<<gProj, thr>>>(ff, ff_W2, ff_b2, bufB, bufA, D_, DFF_, DFF_, DFF_);
    mvln_k<<<gMv, thr>>>(bufA, out, n3_g, n3_b);
}